// round 11
// baseline (speedup 1.0000x reference)
#include <cuda_runtime.h>

#define N_NODES 100000
#define N_EDGES 1000000
#define EV2     (N_EDGES / 2)
#define D 64

// ---------------- scratch (static device globals; no allocation) ----------------
// g_is32 is monotonic: statically 0; set to 1 once if edge_index is int32.
// dtype never changes across replays, so no reset is needed -> deterministic.
__device__ int   g_is32 = 0;
__device__ int   g_deg[N_NODES];
__device__ int   g_off[N_NODES + 1];
__device__ int   g_fill[N_NODES];
__device__ int   g_csr[N_EDGES];
__device__ float g_agg[(size_t)N_NODES * D];
__device__ float g_h[(size_t)N_NODES * D];

// scan scratch
#define SCAN_TPB   256
#define SCAN_CHUNK 1024
#define SCAN_NB    ((N_NODES + SCAN_CHUNK - 1) / SCAN_CHUNK)   // 98
__device__ int g_bsum[SCAN_NB];

// ---------------- f32x2 packed math helpers ----------------
__device__ __forceinline__ unsigned long long pack2(float a) {
    unsigned long long r;
    asm("mov.b64 %0, {%1, %1};" : "=l"(r) : "f"(a));
    return r;
}
__device__ __forceinline__ void fma2(unsigned long long& d, unsigned long long a,
                                     unsigned long long b) {
    asm("fma.rn.f32x2 %0, %1, %2, %0;" : "+l"(d) : "l"(a), "l"(b));
}
__device__ __forceinline__ float2 unpack2(unsigned long long v) {
    float2 f;
    asm("mov.b64 {%0, %1}, %2;" : "=f"(f.x), "=f"(f.y) : "l"(v));
    return f;
}

// ---------------- fused zero + dtype detect ----------------
__global__ void k_init(const int* __restrict__ ei32) {
    int i = blockIdx.x * blockDim.x + threadIdx.x;
    if (i < N_NODES) g_deg[i] = 0;
    if (i < N_EDGES) {
        int hi = ei32[2 * i + 1];
        if (hi != 0) {
            unsigned m = __activemask();
            if ((__ffs(__ballot_sync(m, 1)) - 1) == (int)(threadIdx.x & 31))
                atomicExch(&g_is32, 1);
        }
    }
}

// ---------------- CSR build (2 edges per thread, vector index loads) ----------------
__global__ void k_count(const void* __restrict__ ei) {
    int i = blockIdx.x * blockDim.x + threadIdx.x;
    if (i < EV2) {
        int d0, d1;
        if (g_is32) {
            int2 v = ((const int2*)ei)[EV2 + i];
            d0 = v.x; d1 = v.y;
        } else {
            longlong2 v = ((const longlong2*)ei)[EV2 + i];
            d0 = (int)v.x; d1 = (int)v.y;
        }
        if ((unsigned)d0 < N_NODES) atomicAdd(&g_deg[d0], 1);
        if ((unsigned)d1 < N_NODES) atomicAdd(&g_deg[d1], 1);
    }
}

__global__ void k_bsum() {
    __shared__ int red[SCAN_TPB / 32];
    int b = blockIdx.x, t = threadIdx.x;
    int base = b * SCAN_CHUNK + t * 4;
    int s = 0;
#pragma unroll
    for (int i = 0; i < 4; i++) {
        int idx = base + i;
        if (idx < N_NODES) s += g_deg[idx];
    }
#pragma unroll
    for (int o = 16; o > 0; o >>= 1) s += __shfl_down_sync(0xffffffffu, s, o);
    if ((t & 31) == 0) red[t >> 5] = s;
    __syncthreads();
    if (t < 32) {
        int v = (t < SCAN_TPB / 32) ? red[t] : 0;
#pragma unroll
        for (int o = 16; o > 0; o >>= 1) v += __shfl_down_sync(0xffffffffu, v, o);
        if (t == 0) g_bsum[b] = v;
    }
}

// k_offsets: each block locally scans the 98 block sums (no separate k_scanb launch),
// then computes per-node exclusive offsets for its 1024-node chunk.
__global__ void k_offsets() {
    __shared__ int pres[128];      // scan of block sums
    __shared__ int sm[SCAN_TPB];
    int b = blockIdx.x, t = threadIdx.x;

    // local scan of the 98 block sums (all blocks redundantly; 98 ints from L2)
    if (t < 128) pres[t] = (t < SCAN_NB) ? g_bsum[t] : 0;
    __syncthreads();
#pragma unroll
    for (int o = 1; o < 128; o <<= 1) {
        int v = (t < 128 && t >= o) ? pres[t - o] : 0;
        __syncthreads();
        if (t < 128) pres[t] += v;
        __syncthreads();
    }
    int bpre = (b == 0) ? 0 : pres[b - 1];
    if (b == 0 && t == 0) g_off[N_NODES] = pres[SCAN_NB - 1];

    int base = b * SCAN_CHUNK + t * 4;
    int d0 = 0, d1 = 0, d2 = 0, d3 = 0;
    if (base + 0 < N_NODES) d0 = g_deg[base + 0];
    if (base + 1 < N_NODES) d1 = g_deg[base + 1];
    if (base + 2 < N_NODES) d2 = g_deg[base + 2];
    if (base + 3 < N_NODES) d3 = g_deg[base + 3];
    int tot = d0 + d1 + d2 + d3;
    sm[t] = tot;
    __syncthreads();
#pragma unroll
    for (int o = 1; o < SCAN_TPB; o <<= 1) {
        int v = (t >= o) ? sm[t - o] : 0;
        __syncthreads();
        sm[t] += v;
        __syncthreads();
    }
    int run = bpre + sm[t] - tot;
    if (base + 0 < N_NODES) { g_off[base + 0] = run; g_fill[base + 0] = run; run += d0; }
    if (base + 1 < N_NODES) { g_off[base + 1] = run; g_fill[base + 1] = run; run += d1; }
    if (base + 2 < N_NODES) { g_off[base + 2] = run; g_fill[base + 2] = run; run += d2; }
    if (base + 3 < N_NODES) { g_off[base + 3] = run; g_fill[base + 3] = run; run += d3; }
}

__global__ void k_fill(const void* __restrict__ ei) {
    int i = blockIdx.x * blockDim.x + threadIdx.x;
    if (i < EV2) {
        int s0, s1, d0, d1;
        if (g_is32) {
            int2 sv = ((const int2*)ei)[i];
            int2 dv = ((const int2*)ei)[EV2 + i];
            s0 = sv.x; s1 = sv.y; d0 = dv.x; d1 = dv.y;
        } else {
            longlong2 sv = ((const longlong2*)ei)[i];
            longlong2 dv = ((const longlong2*)ei)[EV2 + i];
            s0 = (int)sv.x; s1 = (int)sv.y; d0 = (int)dv.x; d1 = (int)dv.y;
        }
        if ((unsigned)d0 < N_NODES && (unsigned)s0 < N_NODES) {
            int pos = atomicAdd(&g_fill[d0], 1);
            if ((unsigned)pos < N_EDGES) g_csr[pos] = s0;
        }
        if ((unsigned)d1 < N_NODES && (unsigned)s1 < N_NODES) {
            int pos = atomicAdd(&g_fill[d1], 1);
            if ((unsigned)pos < N_EDGES) g_csr[pos] = s1;
        }
    }
}

// ---------------- gather-mean aggregation ----------------
// One warp per node; lanes split in halves (each half covers a 64-float row as
// 16 float4 lanes). Manual 4-edge unroll: two independent LDG.128 chains in
// flight per iteration to raise MLP (latency-bound otherwise).
__global__ void k_aggregate(const float* __restrict__ xin, int use_h) {
    int node = (blockIdx.x * blockDim.x + threadIdx.x) >> 5;
    if (node >= N_NODES) return;
    int lane = threadIdx.x & 31;
    int half = lane >> 4;
    int l16  = lane & 15;
    const float* feat = use_h ? (const float*)g_h : xin;
    int s0 = g_off[node], s1 = g_off[node + 1];

    float4 accA = make_float4(0.f, 0.f, 0.f, 0.f);
    float4 accB = make_float4(0.f, 0.f, 0.f, 0.f);
    int e = s0;
    for (; e + 4 <= s1; e += 4) {
        int iA = g_csr[e + half];
        int iB = g_csr[e + 2 + half];
        float4 vA = *(const float4*)&feat[(size_t)iA * D + l16 * 4];
        float4 vB = *(const float4*)&feat[(size_t)iB * D + l16 * 4];
        accA.x += vA.x; accA.y += vA.y; accA.z += vA.z; accA.w += vA.w;
        accB.x += vB.x; accB.y += vB.y; accB.z += vB.z; accB.w += vB.w;
    }
    if (e + 2 <= s1) {
        int iA = g_csr[e + half];
        float4 vA = *(const float4*)&feat[(size_t)iA * D + l16 * 4];
        accA.x += vA.x; accA.y += vA.y; accA.z += vA.z; accA.w += vA.w;
        e += 2;
    }
    if (e < s1 && half == 0) {
        int iA = g_csr[e];
        float4 vA = *(const float4*)&feat[(size_t)iA * D + l16 * 4];
        accB.x += vA.x; accB.y += vA.y; accB.z += vA.z; accB.w += vA.w;
    }
    accA.x += accB.x; accA.y += accB.y; accA.z += accB.z; accA.w += accB.w;
    accA.x += __shfl_xor_sync(0xffffffffu, accA.x, 16);
    accA.y += __shfl_xor_sync(0xffffffffu, accA.y, 16);
    accA.z += __shfl_xor_sync(0xffffffffu, accA.z, 16);
    accA.w += __shfl_xor_sync(0xffffffffu, accA.w, 16);
    if (half == 0) {
        float inv = 1.0f / fmaxf((float)(s1 - s0), 1.0f);
        float4 r = make_float4(accA.x * inv, accA.y * inv, accA.z * inv, accA.w * inv);
        *(float4*)&g_agg[(size_t)node * D + l16 * 4] = r;
    }
}

// ---------------- fused combine: out = agg@Wl^T + root@Wr^T + b (opt relu) ----------
#define MT      32
#define WSTR    68
#define ASTR    68
#define TILES   5
#define CMB_BLOCKS ((N_NODES + MT * TILES - 1) / (MT * TILES))   // 625

__global__ void k_combine(const float* __restrict__ xin,
                          const float* __restrict__ Wl, const float* __restrict__ bl,
                          const float* __restrict__ Wr,
                          float* __restrict__ outp, int layer)
{
    __shared__ float Wt[128][WSTR];
    __shared__ float As[MT][ASTR];
    __shared__ float bs[64];

    int t = threadIdx.x;

    const float* root = (layer == 1) ? xin : (const float*)g_h;
    float* out = (layer == 1) ? (float*)g_h : outp;

    for (int i = t; i < 64 * 64; i += 256) {
        int j = i >> 6;
        int k = i & 63;
        Wt[k][j]      = Wl[i];
        Wt[64 + k][j] = Wr[i];
    }
    if (t < 64) bs[t] = bl[t];

    int tx = t & 15;
    int ty = t >> 4;
    int j0 = tx * 4;
    int m0 = ty * 2;
    int relu = (layer == 1);

    __syncthreads();
    float4 bias = *(const float4*)&bs[j0];

    for (int tile = 0; tile < TILES; tile++) {
        int base = (blockIdx.x * TILES + tile) * MT;
        if (base >= N_NODES) break;

        unsigned long long a001 = 0ull, a023 = 0ull, a101 = 0ull, a123 = 0ull;

        for (int i = t; i < MT * 16; i += 256) {
            int m  = i >> 4;
            int c4 = i & 15;
            int node = base + m;
            float4 v = make_float4(0.f, 0.f, 0.f, 0.f);
            if (node < N_NODES) v = *(const float4*)&g_agg[(size_t)node * D + c4 * 4];
            *(float4*)&As[m][c4 * 4] = v;
        }
        __syncthreads();
#pragma unroll 8
        for (int k = 0; k < 64; k++) {
            ulonglong2 wp = *(const ulonglong2*)&Wt[k][j0];
            unsigned long long a0 = pack2(As[m0][k]);
            unsigned long long a1 = pack2(As[m0 + 1][k]);
            fma2(a001, a0, wp.x); fma2(a023, a0, wp.y);
            fma2(a101, a1, wp.x); fma2(a123, a1, wp.y);
        }
        __syncthreads();

        for (int i = t; i < MT * 16; i += 256) {
            int m  = i >> 4;
            int c4 = i & 15;
            int node = base + m;
            float4 v = make_float4(0.f, 0.f, 0.f, 0.f);
            if (node < N_NODES) v = *(const float4*)&root[(size_t)node * D + c4 * 4];
            *(float4*)&As[m][c4 * 4] = v;
        }
        __syncthreads();
#pragma unroll 8
        for (int k = 0; k < 64; k++) {
            ulonglong2 wp = *(const ulonglong2*)&Wt[64 + k][j0];
            unsigned long long a0 = pack2(As[m0][k]);
            unsigned long long a1 = pack2(As[m0 + 1][k]);
            fma2(a001, a0, wp.x); fma2(a023, a0, wp.y);
            fma2(a101, a1, wp.x); fma2(a123, a1, wp.y);
        }

        float2 r01 = unpack2(a001), r23 = unpack2(a023);
        float2 s01 = unpack2(a101), s23 = unpack2(a123);

        int n0 = base + m0;
        if (n0 < N_NODES) {
            float4 r;
            r.x = r01.x + bias.x; r.y = r01.y + bias.y;
            r.z = r23.x + bias.z; r.w = r23.y + bias.w;
            if (relu) {
                r.x = fmaxf(r.x, 0.f); r.y = fmaxf(r.y, 0.f);
                r.z = fmaxf(r.z, 0.f); r.w = fmaxf(r.w, 0.f);
            }
            *(float4*)&out[(size_t)n0 * D + j0] = r;
        }
        int n1 = base + m0 + 1;
        if (n1 < N_NODES) {
            float4 r;
            r.x = s01.x + bias.x; r.y = s01.y + bias.y;
            r.z = s23.x + bias.z; r.w = s23.y + bias.w;
            if (relu) {
                r.x = fmaxf(r.x, 0.f); r.y = fmaxf(r.y, 0.f);
                r.z = fmaxf(r.z, 0.f); r.w = fmaxf(r.w, 0.f);
            }
            *(float4*)&out[(size_t)n1 * D + j0] = r;
        }
        __syncthreads();
    }
}

// ---------------- launch: kernel launches ONLY ----------------
extern "C" void kernel_launch(void* const* d_in, const int* in_sizes, int n_in,
                              void* d_out, int out_size) {
    const float* x   = (const float*)d_in[0];
    const void*  ei  = d_in[1];
    const float* W1l = (const float*)d_in[2];
    const float* b1l = (const float*)d_in[3];
    const float* W1r = (const float*)d_in[4];
    const float* W2l = (const float*)d_in[5];
    const float* b2l = (const float*)d_in[6];
    const float* W2r = (const float*)d_in[7];
    float* out = (float*)d_out;

    k_init<<<(N_EDGES + 255) / 256, 256>>>((const int*)ei);
    k_count<<<(EV2 + 255) / 256, 256>>>(ei);
    k_bsum<<<SCAN_NB, SCAN_TPB>>>();
    k_offsets<<<SCAN_NB, SCAN_TPB>>>();
    k_fill<<<(EV2 + 255) / 256, 256>>>(ei);

    const int AGG_BLOCKS = (N_NODES + 7) / 8;

    // layer 1
    k_aggregate<<<AGG_BLOCKS, 256>>>(x, 0);
    k_combine<<<CMB_BLOCKS, 256>>>(x, W1l, b1l, W1r, nullptr, 1);

    // layer 2
    k_aggregate<<<AGG_BLOCKS, 256>>>(nullptr, 1);
    k_combine<<<CMB_BLOCKS, 256>>>(nullptr, W2l, b2l, W2r, out, 2);
}

// round 12
// speedup vs baseline: 1.1171x; 1.1171x over previous
#include <cuda_runtime.h>

#define N_NODES 100000
#define N_EDGES 1000000
#define EV2     (N_EDGES / 2)
#define D 64

// ---------------- scratch (static device globals; no allocation) ----------------
// g_is32 is monotonic: statically 0; set to 1 once if edge_index is int32.
__device__ int   g_is32 = 0;
__device__ int   g_deg[N_NODES];
__device__ int   g_off[N_NODES + 1];
__device__ int   g_fill[N_NODES];
__device__ int   g_csr[N_EDGES];
__device__ float g_h[(size_t)N_NODES * D];

// scan scratch
#define SCAN_TPB   256
#define SCAN_CHUNK 1024
#define SCAN_NB    ((N_NODES + SCAN_CHUNK - 1) / SCAN_CHUNK)   // 98
__device__ int g_bsum[SCAN_NB];

// ---------------- f32x2 packed math helpers ----------------
__device__ __forceinline__ unsigned long long pack2(float a) {
    unsigned long long r;
    asm("mov.b64 %0, {%1, %1};" : "=l"(r) : "f"(a));
    return r;
}
__device__ __forceinline__ void fma2(unsigned long long& d, unsigned long long a,
                                     unsigned long long b) {
    asm("fma.rn.f32x2 %0, %1, %2, %0;" : "+l"(d) : "l"(a), "l"(b));
}
__device__ __forceinline__ float2 unpack2(unsigned long long v) {
    float2 f;
    asm("mov.b64 {%0, %1}, %2;" : "=f"(f.x), "=f"(f.y) : "l"(v));
    return f;
}

// ---------------- fused zero + dtype detect ----------------
__global__ void k_init(const int* __restrict__ ei32) {
    int i = blockIdx.x * blockDim.x + threadIdx.x;
    if (i < N_NODES) g_deg[i] = 0;
    if (i < N_EDGES) {
        int hi = ei32[2 * i + 1];
        if (hi != 0) {
            unsigned m = __activemask();
            if ((__ffs(__ballot_sync(m, 1)) - 1) == (int)(threadIdx.x & 31))
                atomicExch(&g_is32, 1);
        }
    }
}

// ---------------- CSR build ----------------
__global__ void k_count(const void* __restrict__ ei) {
    int i = blockIdx.x * blockDim.x + threadIdx.x;
    if (i < EV2) {
        int d0, d1;
        if (g_is32) {
            int2 v = ((const int2*)ei)[EV2 + i];
            d0 = v.x; d1 = v.y;
        } else {
            longlong2 v = ((const longlong2*)ei)[EV2 + i];
            d0 = (int)v.x; d1 = (int)v.y;
        }
        if ((unsigned)d0 < N_NODES) atomicAdd(&g_deg[d0], 1);
        if ((unsigned)d1 < N_NODES) atomicAdd(&g_deg[d1], 1);
    }
}

__global__ void k_bsum() {
    __shared__ int red[SCAN_TPB / 32];
    int b = blockIdx.x, t = threadIdx.x;
    int base = b * SCAN_CHUNK + t * 4;
    int s = 0;
#pragma unroll
    for (int i = 0; i < 4; i++) {
        int idx = base + i;
        if (idx < N_NODES) s += g_deg[idx];
    }
#pragma unroll
    for (int o = 16; o > 0; o >>= 1) s += __shfl_down_sync(0xffffffffu, s, o);
    if ((t & 31) == 0) red[t >> 5] = s;
    __syncthreads();
    if (t < 32) {
        int v = (t < SCAN_TPB / 32) ? red[t] : 0;
#pragma unroll
        for (int o = 16; o > 0; o >>= 1) v += __shfl_down_sync(0xffffffffu, v, o);
        if (t == 0) g_bsum[b] = v;
    }
}

// k_offsets: each block locally scans the 98 block sums, then per-node offsets.
__global__ void k_offsets() {
    __shared__ int pres[128];
    __shared__ int sm[SCAN_TPB];
    int b = blockIdx.x, t = threadIdx.x;

    if (t < 128) pres[t] = (t < SCAN_NB) ? g_bsum[t] : 0;
    __syncthreads();
#pragma unroll
    for (int o = 1; o < 128; o <<= 1) {
        int v = (t < 128 && t >= o) ? pres[t - o] : 0;
        __syncthreads();
        if (t < 128) pres[t] += v;
        __syncthreads();
    }
    int bpre = (b == 0) ? 0 : pres[b - 1];
    if (b == 0 && t == 0) g_off[N_NODES] = pres[SCAN_NB - 1];

    int base = b * SCAN_CHUNK + t * 4;
    int d0 = 0, d1 = 0, d2 = 0, d3 = 0;
    if (base + 0 < N_NODES) d0 = g_deg[base + 0];
    if (base + 1 < N_NODES) d1 = g_deg[base + 1];
    if (base + 2 < N_NODES) d2 = g_deg[base + 2];
    if (base + 3 < N_NODES) d3 = g_deg[base + 3];
    int tot = d0 + d1 + d2 + d3;
    sm[t] = tot;
    __syncthreads();
#pragma unroll
    for (int o = 1; o < SCAN_TPB; o <<= 1) {
        int v = (t >= o) ? sm[t - o] : 0;
        __syncthreads();
        sm[t] += v;
        __syncthreads();
    }
    int run = bpre + sm[t] - tot;
    if (base + 0 < N_NODES) { g_off[base + 0] = run; g_fill[base + 0] = run; run += d0; }
    if (base + 1 < N_NODES) { g_off[base + 1] = run; g_fill[base + 1] = run; run += d1; }
    if (base + 2 < N_NODES) { g_off[base + 2] = run; g_fill[base + 2] = run; run += d2; }
    if (base + 3 < N_NODES) { g_off[base + 3] = run; g_fill[base + 3] = run; run += d3; }
}

__global__ void k_fill(const void* __restrict__ ei) {
    int i = blockIdx.x * blockDim.x + threadIdx.x;
    if (i < EV2) {
        int s0, s1, d0, d1;
        if (g_is32) {
            int2 sv = ((const int2*)ei)[i];
            int2 dv = ((const int2*)ei)[EV2 + i];
            s0 = sv.x; s1 = sv.y; d0 = dv.x; d1 = dv.y;
        } else {
            longlong2 sv = ((const longlong2*)ei)[i];
            longlong2 dv = ((const longlong2*)ei)[EV2 + i];
            s0 = (int)sv.x; s1 = (int)sv.y; d0 = (int)dv.x; d1 = (int)dv.y;
        }
        if ((unsigned)d0 < N_NODES && (unsigned)s0 < N_NODES) {
            int pos = atomicAdd(&g_fill[d0], 1);
            if ((unsigned)pos < N_EDGES) g_csr[pos] = s0;
        }
        if ((unsigned)d1 < N_NODES && (unsigned)s1 < N_NODES) {
            int pos = atomicAdd(&g_fill[d1], 1);
            if ((unsigned)pos < N_EDGES) g_csr[pos] = s1;
        }
    }
}

// ---------------- fused layer: agg(feat) @ Wl^T + feat @ Wr^T + b (opt relu) ------
// Block = 256 threads, stages weights once, loops over TILES tiles of MT=32 nodes.
// Per tile: (1) each warp mean-aggregates 4 nodes straight into As smem (half-warp
// float4 gather + shfl-xor(16) reduce, R7 scheme), (2) FMA pass over Wl^T,
// (3) stage root rows, (4) FMA pass over Wr^T, write out.
#define MT      32
#define WSTR    68
#define ASTR    68
#define TILES   5
#define CMB_BLOCKS ((N_NODES + MT * TILES - 1) / (MT * TILES))   // 625

__global__ void __launch_bounds__(256) k_layer(
    const float* __restrict__ xin,
    const float* __restrict__ Wl, const float* __restrict__ bl,
    const float* __restrict__ Wr,
    float* __restrict__ outp, int layer)
{
    __shared__ float Wt[128][WSTR];
    __shared__ float As[MT][ASTR];
    __shared__ float bs[64];

    int t = threadIdx.x;
    const float* feat = (layer == 1) ? xin : (const float*)g_h;  // agg + root source
    float* out = (layer == 1) ? (float*)g_h : outp;

    // stage weights once per block
    for (int i = t; i < 64 * 64; i += 256) {
        int j = i >> 6;
        int k = i & 63;
        Wt[k][j]      = Wl[i];
        Wt[64 + k][j] = Wr[i];
    }
    if (t < 64) bs[t] = bl[t];

    int wid  = t >> 5;
    int lane = t & 31;
    int half = lane >> 4;
    int l16  = lane & 15;

    int tx = t & 15;
    int ty = t >> 4;
    int j0 = tx * 4;
    int m0 = ty * 2;
    int relu = (layer == 1);

    __syncthreads();
    float4 bias = *(const float4*)&bs[j0];

    for (int tile = 0; tile < TILES; tile++) {
        int base = (blockIdx.x * TILES + tile) * MT;
        if (base >= N_NODES) break;

        // ---- (1) aggregate 32 nodes into As: warp wid handles nodes 4*wid..4*wid+3
#pragma unroll
        for (int mm = 0; mm < 4; mm++) {
            int m = wid * 4 + mm;
            int node = base + m;
            float4 acc = make_float4(0.f, 0.f, 0.f, 0.f);
            float inv = 0.f;
            if (node < N_NODES) {
                int s0 = g_off[node], s1 = g_off[node + 1];
                int e = s0;
                for (; e + 2 <= s1; e += 2) {
                    int s = g_csr[e + half];
                    float4 v = *(const float4*)&feat[(size_t)s * D + l16 * 4];
                    acc.x += v.x; acc.y += v.y; acc.z += v.z; acc.w += v.w;
                }
                if (e < s1 && half == 0) {
                    int s = g_csr[e];
                    float4 v = *(const float4*)&feat[(size_t)s * D + l16 * 4];
                    acc.x += v.x; acc.y += v.y; acc.z += v.z; acc.w += v.w;
                }
                inv = 1.0f / fmaxf((float)(s1 - s0), 1.0f);
            }
            acc.x += __shfl_xor_sync(0xffffffffu, acc.x, 16);
            acc.y += __shfl_xor_sync(0xffffffffu, acc.y, 16);
            acc.z += __shfl_xor_sync(0xffffffffu, acc.z, 16);
            acc.w += __shfl_xor_sync(0xffffffffu, acc.w, 16);
            if (half == 0) {
                float4 r = make_float4(acc.x * inv, acc.y * inv, acc.z * inv, acc.w * inv);
                *(float4*)&As[m][l16 * 4] = r;
            }
        }
        __syncthreads();

        // ---- (2) FMA pass 1: Wl^T over aggregated rows
        unsigned long long a001 = 0ull, a023 = 0ull, a101 = 0ull, a123 = 0ull;
#pragma unroll 8
        for (int k = 0; k < 64; k++) {
            ulonglong2 wp = *(const ulonglong2*)&Wt[k][j0];
            unsigned long long a0 = pack2(As[m0][k]);
            unsigned long long a1 = pack2(As[m0 + 1][k]);
            fma2(a001, a0, wp.x); fma2(a023, a0, wp.y);
            fma2(a101, a1, wp.x); fma2(a123, a1, wp.y);
        }
        __syncthreads();

        // ---- (3) stage root rows
        for (int i = t; i < MT * 16; i += 256) {
            int m  = i >> 4;
            int c4 = i & 15;
            int node = base + m;
            float4 v = make_float4(0.f, 0.f, 0.f, 0.f);
            if (node < N_NODES) v = *(const float4*)&feat[(size_t)node * D + c4 * 4];
            *(float4*)&As[m][c4 * 4] = v;
        }
        __syncthreads();

        // ---- (4) FMA pass 2: Wr^T over root rows
#pragma unroll 8
        for (int k = 0; k < 64; k++) {
            ulonglong2 wp = *(const ulonglong2*)&Wt[64 + k][j0];
            unsigned long long a0 = pack2(As[m0][k]);
            unsigned long long a1 = pack2(As[m0 + 1][k]);
            fma2(a001, a0, wp.x); fma2(a023, a0, wp.y);
            fma2(a101, a1, wp.x); fma2(a123, a1, wp.y);
        }

        float2 r01 = unpack2(a001), r23 = unpack2(a023);
        float2 s01 = unpack2(a101), s23 = unpack2(a123);

        int n0 = base + m0;
        if (n0 < N_NODES) {
            float4 r;
            r.x = r01.x + bias.x; r.y = r01.y + bias.y;
            r.z = r23.x + bias.z; r.w = r23.y + bias.w;
            if (relu) {
                r.x = fmaxf(r.x, 0.f); r.y = fmaxf(r.y, 0.f);
                r.z = fmaxf(r.z, 0.f); r.w = fmaxf(r.w, 0.f);
            }
            *(float4*)&out[(size_t)n0 * D + j0] = r;
        }
        int n1 = base + m0 + 1;
        if (n1 < N_NODES) {
            float4 r;
            r.x = s01.x + bias.x; r.y = s01.y + bias.y;
            r.z = s23.x + bias.z; r.w = s23.y + bias.w;
            if (relu) {
                r.x = fmaxf(r.x, 0.f); r.y = fmaxf(r.y, 0.f);
                r.z = fmaxf(r.z, 0.f); r.w = fmaxf(r.w, 0.f);
            }
            *(float4*)&out[(size_t)n1 * D + j0] = r;
        }
        __syncthreads();
    }
}

// ---------------- launch: kernel launches ONLY ----------------
extern "C" void kernel_launch(void* const* d_in, const int* in_sizes, int n_in,
                              void* d_out, int out_size) {
    const float* x   = (const float*)d_in[0];
    const void*  ei  = d_in[1];
    const float* W1l = (const float*)d_in[2];
    const float* b1l = (const float*)d_in[3];
    const float* W1r = (const float*)d_in[4];
    const float* W2l = (const float*)d_in[5];
    const float* b2l = (const float*)d_in[6];
    const float* W2r = (const float*)d_in[7];
    float* out = (float*)d_out;

    k_init<<<(N_EDGES + 255) / 256, 256>>>((const int*)ei);
    k_count<<<(EV2 + 255) / 256, 256>>>(ei);
    k_bsum<<<SCAN_NB, SCAN_TPB>>>();
    k_offsets<<<SCAN_NB, SCAN_TPB>>>();
    k_fill<<<(EV2 + 255) / 256, 256>>>(ei);

    // layer 1 (fused aggregate + combine)
    k_layer<<<CMB_BLOCKS, 256>>>(x, W1l, b1l, W1r, nullptr, 1);
    // layer 2
    k_layer<<<CMB_BLOCKS, 256>>>(nullptr, W2l, b2l, W2r, out, 2);
}